// round 6
// baseline (speedup 1.0000x reference)
#include <cuda_runtime.h>
#include <stdint.h>

// Problem constants (fixed shapes from reference)
#define Kc   512               // codebook size
#define Dc   8                 // embedding dim / channels
#define Sc   110592            // 48*48*48
#define Bc   2                 // batch
#define Nc   (Bc * Sc)         // 221184 voxels
#define TPB  256               // threads per block (8 warps)
#define VPB  512               // voxels per block (2 per thread, sets A and B)
#define NBLK (Nc / VPB)        // 432 blocks
#define NPAIR 256              // codebook pairs (Kc/2)
#define O_OUT 1                // out tensor offset (after scalar loss)
#define O_ENC (1 + Nc * Dc)    // encodings offset = 1769473 (== 1 mod 4)

__device__ float    g_sum   = 0.0f;   // reset by last block each run
__device__ unsigned g_count = 0u;

// ---- packed f32x2 helpers (per-lane rounding identical to scalar chain) ----
__device__ __forceinline__ unsigned long long pk2(float lo, float hi) {
    unsigned long long r;
    asm("mov.b64 %0, {%1, %2};" : "=l"(r) : "f"(lo), "f"(hi));
    return r;
}
__device__ __forceinline__ unsigned long long mul2(unsigned long long a, unsigned long long b) {
    unsigned long long d;
    asm("mul.rn.f32x2 %0, %1, %2;" : "=l"(d) : "l"(a), "l"(b));
    return d;
}
__device__ __forceinline__ unsigned long long add2(unsigned long long a, unsigned long long b) {
    unsigned long long d;
    asm("add.rn.f32x2 %0, %1, %2;" : "=l"(d) : "l"(a), "l"(b));
    return d;
}
__device__ __forceinline__ unsigned long long fma2(unsigned long long a, unsigned long long b, unsigned long long c) {
    unsigned long long d;
    asm("fma.rn.f32x2 %0, %1, %2, %3;" : "=l"(d) : "l"(a), "l"(b), "l"(c));
    return d;
}
__device__ __forceinline__ void upk2(unsigned long long v, float& lo, float& hi) {
    asm("mov.b64 {%0, %1}, %2;" : "=f"(lo), "=f"(hi) : "l"(v));
}

struct VoxResult { int bi; float acc; };

// Argmin over the codebook for one voxel with the bit-exact rounding chain,
// then write quantized out + accumulate MSE. Returns chosen index.
__device__ __forceinline__ VoxResult process_voxel(
    const ulonglong2* __restrict__ sEp, const float* __restrict__ sE2,
    const float* __restrict__ xp, float* __restrict__ op, float accIn)
{
    float xv[8];
#pragma unroll
    for (int c = 0; c < 8; c++) xv[c] = xp[(size_t)c * Sc];

    unsigned long long xq[8];
#pragma unroll
    for (int c = 0; c < 8; c++) xq[c] = pk2(xv[c], xv[c]);

    // sum(x^2): square then sequential add (match reference rounding chain)
    float s2 = __fmul_rn(xv[0], xv[0]);
#pragma unroll
    for (int c = 1; c < 8; c++) s2 = __fadd_rn(s2, __fmul_rn(xv[c], xv[c]));
    const unsigned long long sx2 = pk2(s2, s2);
    const unsigned long long n2  = pk2(-2.0f, -2.0f);

    float best = 3.4e38f;
    int   bi   = 0;
#pragma unroll 4
    for (int p = 0; p < NPAIR; p++) {
        ulonglong2 v0 = sEp[p * 4 + 0];
        ulonglong2 v1 = sEp[p * 4 + 1];
        ulonglong2 v2 = sEp[p * 4 + 2];
        ulonglong2 v3 = sEp[p * 4 + 3];

        unsigned long long t = mul2(xq[0], v0.x);
        t = fma2(xq[1], v0.y, t);
        t = fma2(xq[2], v1.x, t);
        t = fma2(xq[3], v1.y, t);
        t = fma2(xq[4], v2.x, t);
        t = fma2(xq[5], v2.y, t);
        t = fma2(xq[6], v3.x, t);
        t = fma2(xq[7], v3.y, t);

        unsigned long long e2 = *(const unsigned long long*)&sE2[2 * p];
        unsigned long long d  = fma2(n2, t, add2(sx2, e2));
        float dl, dh;
        upk2(d, dl, dh);
        if (dl < best) { best = dl; bi = 2 * p; }       // strict <: lowest index
        if (dh < best) { best = dh; bi = 2 * p + 1; }
    }

    // quantized out (forward STE == quantized) + MSE accumulation
    const float* sf = (const float*)sEp;
    const int p = bi >> 1, l = bi & 1;
    float acc = accIn;
#pragma unroll
    for (int c = 0; c < 8; c++) {
        float q = sf[p * 16 + (c >> 1) * 4 + (c & 1) * 2 + l];
        op[(size_t)c * Sc] = q;
        float dd = xv[c] - q;
        acc = fmaf(dd, dd, acc);
    }
    VoxResult r; r.bi = bi; r.acc = acc;
    return r;
}

// Warp-cooperative: write 32 complete one-hot rows (this warp's voxels).
// Row base float index == 1 mod 4 -> aligned float4 region covers floats
// [3, 511); floats 0..2 and 511 are owner-lane scalars.
__device__ __forceinline__ void write_rows(float* __restrict__ encW, int bi, int lane)
{
    const float4 z4 = make_float4(0.f, 0.f, 0.f, 0.f);
#pragma unroll 1
    for (int r = 0; r < 32; r++) {
        int t  = __shfl_sync(0xFFFFFFFFu, bi, r);
        int tq = (int)(((unsigned)(t - 3)) >> 2);   // float4 slot holding t (if t>=3)
        float* rp = encW + (size_t)r * Kc;
#pragma unroll
        for (int seg = 0; seg < 4; seg++) {
            int q = seg * 32 + lane;                // float4 slot 0..127
            if (q < 127) {
                float4 v = z4;
                if (q == tq) {                      // taken by 1 lane in 1 seg
                    int c = (t - 3) & 3;
                    v.x = (c == 0) ? 1.0f : 0.0f;
                    v.y = (c == 1) ? 1.0f : 0.0f;
                    v.z = (c == 2) ? 1.0f : 0.0f;
                    v.w = (c == 3) ? 1.0f : 0.0f;
                }
                *(float4*)(rp + 3 + q * 4) = v;
            }
        }
    }
    // own row's head (0..2) and tail (511) scalars
    float* rp = encW + (size_t)lane * Kc;
    rp[0]   = (bi == 0)   ? 1.0f : 0.0f;
    rp[1]   = (bi == 1)   ? 1.0f : 0.0f;
    rp[2]   = (bi == 2)   ? 1.0f : 0.0f;
    rp[511] = (bi == 511) ? 1.0f : 0.0f;
}

__global__ __launch_bounds__(TPB, 4) void vq_main_kernel(
    const float* __restrict__ x,
    const float* __restrict__ ew,
    float* __restrict__ out)
{
    // Pair-interleaved codebook: pair p, coord c -> (e[2p][c], e[2p+1][c]).
    __shared__ ulonglong2 sEp[NPAIR * 4];   // 16 KB
    __shared__ float      sE2[Kc];          // 2 KB
    __shared__ float      sRed[TPB / 32];
    __shared__ int        sLast;

    const int tid  = threadIdx.x;
    const int wid  = tid >> 5;
    const int lane = tid & 31;

    // ---- Phase 1a: build pair-packed codebook in shared
    {
        float* sf = (float*)sEp;
        for (int idx = tid; idx < NPAIR * Dc; idx += TPB) {
            int p = idx >> 3, c = idx & 7;
            float lo = ew[(2 * p) * Dc + c];
            float hi = ew[(2 * p + 1) * Dc + c];
            int base = p * 16 + (c >> 1) * 4 + (c & 1) * 2;
            sf[base]     = lo;
            sf[base + 1] = hi;
        }
    }
    // ---- Phase 1b: per-entry sum of squares, sequential fp32 (match jnp.sum(e**2))
    for (int k = tid; k < Kc; k += TPB) {
        float4 a = *(const float4*)(ew + (size_t)k * Dc);
        float4 b = *(const float4*)(ew + (size_t)k * Dc + 4);
        float s = __fmul_rn(a.x, a.x);
        s = __fadd_rn(s, __fmul_rn(a.y, a.y));
        s = __fadd_rn(s, __fmul_rn(a.z, a.z));
        s = __fadd_rn(s, __fmul_rn(a.w, a.w));
        s = __fadd_rn(s, __fmul_rn(b.x, b.x));
        s = __fadd_rn(s, __fmul_rn(b.y, b.y));
        s = __fadd_rn(s, __fmul_rn(b.z, b.z));
        s = __fadd_rn(s, __fmul_rn(b.w, b.w));
        sE2[k] = s;
    }
    __syncthreads();

    const int bb = (blockIdx.x * VPB) >= Sc ? 1 : 0;   // batch split is block-aligned
    const int n0 = blockIdx.x * VPB + tid;             // set A voxel
    const int n1 = n0 + TPB;                           // set B voxel
    const float* xbase = x + (size_t)bb * (Dc * Sc);
    float* obase = out + O_OUT + (size_t)bb * (Dc * Sc);

    float acc = 0.0f;

    // ---- Set A: argmin -> quantized out -> stream 32 complete one-hot rows
    {
        VoxResult r = process_voxel(sEp, sE2, xbase + (n0 - bb * Sc),
                                    obase + (n0 - bb * Sc), acc);
        acc = r.acc;
        float* encW = out + O_ENC + (size_t)(blockIdx.x * VPB + wid * 32) * Kc;
        write_rows(encW, r.bi, lane);
    }

    // ---- Set B: same
    {
        VoxResult r = process_voxel(sEp, sE2, xbase + (n1 - bb * Sc),
                                    obase + (n1 - bb * Sc), acc);
        acc = r.acc;
        float* encW = out + O_ENC + (size_t)(blockIdx.x * VPB + TPB + wid * 32) * Kc;
        write_rows(encW, r.bi, lane);
    }

    // ---- Block-reduce squared error; last block finalizes the loss
#pragma unroll
    for (int o = 16; o > 0; o >>= 1) acc += __shfl_down_sync(0xFFFFFFFFu, acc, o);
    if (lane == 0) sRed[wid] = acc;
    __syncthreads();
    if (tid == 0) {
        float v = 0.0f;
#pragma unroll
        for (int w = 0; w < TPB / 32; w++) v += sRed[w];
        atomicAdd(&g_sum, v);
        __threadfence();
        unsigned t = atomicAdd(&g_count, 1u);
        sLast = (t == NBLK - 1) ? 1 : 0;
    }
    __syncthreads();
    if (sLast && tid == 0) {
        float tot = *((volatile float*)&g_sum);
        float m = tot / (float)((size_t)Nc * Dc);
        m = fminf(fmaxf(m, 0.0f), 10.0f);
        out[0] = 1.25f * m;      // q_latent + BETA * e_latent (identical forward)
        g_sum = 0.0f;            // reset for next graph replay
        g_count = 0u;
    }
}

extern "C" void kernel_launch(void* const* d_in, const int* in_sizes, int n_in,
                              void* d_out, int out_size)
{
    const float* x  = (const float*)d_in[0];
    const float* ew = (const float*)d_in[1];
    float* out = (float*)d_out;

    vq_main_kernel<<<NBLK, TPB>>>(x, ew, out);
}